// round 17
// baseline (speedup 1.0000x reference)
#include <cuda_runtime.h>
#include <cuda_bf16.h>

// ChannelPolyLayer: out[b,o,x,y] = sum_c coeffs[b,o,c] * prod_v img[b,v,x,y]^powers[c,v]
// DEGREE=3, NUM_VARS=3, NUM_OUT=3, NUM_COEFFS=20, BATCH=16, H=W=512.
//
// Monomial order from _generate_powers(3,3):
//  0:1  1:v0  2:v1  3:v2  4:v0^2  5:v0v1  6:v0v2  7:v1^2  8:v1v2  9:v2^2
// 10:v0^3 11:v0^2v1 12:v0^2v2 13:v0v1^2 14:v0v1v2 15:v0v2^2
// 16:v1^3 17:v1^2v2 18:v1v2^2 19:v2^3
//
// FINAL (R17): the measured champion configuration (R6/R11, 16.86-16.90us
// wall over 16 rounds of structural search).
//  - Nested Horner, packed fma.rn.f32x2 (19 per output per pixel-pair);
//    FMA-busy at its 6.4us floor.
//  - Persistent one-wave grid: 288 CTAs (18x16) x 256 threads at 2 CTAs/SM
//    (load-balanced across 148 SMs; wall ~= ncu - 0.2us vs +2.1us for
//    multi-wave grids).
//  - batch = blockIdx.y: no batch decode in the loop; one-batch coeffs
//    splatted to {c,c} pairs in shared (480 B, LDS.64 broadcast).
//  - Continuous MLP=6: next item's 6 LDG.128 issued before computing the
//    current item; loads outstanding during the whole compute phase.
//  - No reg cap (R5: caps break FFMA2 operand pairing), no per-iteration
//    barriers (R14), no cp.async (R9), plain STG (.cs proven neutral, R11).

#define HW_PIX (512 * 512)
#define PLANE4 (HW_PIX / 4)       // 65536 float4s per channel plane
#define HALF4  (PLANE4 / 2)       // 32768 items; item j covers float4 j, j+HALF4
#define NBATCH 16
#define NCOEF  20
#define TPB    256
#define CTAS_X 18                 // 18*16 = 288 CTAs ~= one balanced wave at 2/SM
#define STRIDE (CTAS_X * TPB)     // 4608

typedef unsigned long long ull;

__device__ __forceinline__ ull ffma2(ull a, ull b, ull c) {
    ull d;
    asm("fma.rn.f32x2 %0, %1, %2, %3;" : "=l"(d) : "l"(a), "l"(b), "l"(c));
    return d;
}

// Horner over a packed pair of pixels. c[] are {coeff,coeff} splat pairs.
__device__ __forceinline__ ull horner2(ull v0, ull v1, ull v2,
                                       const ull* __restrict__ c) {
    ull pA = ffma2(c[16], v1, c[7]);
    pA = ffma2(v1, pA, c[2]);
    pA = ffma2(v1, pA, c[0]);
    ull pB = ffma2(c[17], v1, c[8]);
    pB = ffma2(v1, pB, c[3]);
    ull pC = ffma2(c[18], v1, c[9]);
    ull C0 = ffma2(c[19], v2, pC);
    C0 = ffma2(C0, v2, pB);
    C0 = ffma2(C0, v2, pA);
    ull qA = ffma2(c[13], v1, c[5]);
    qA = ffma2(v1, qA, c[1]);
    ull qB = ffma2(c[14], v1, c[6]);
    ull C1 = ffma2(c[15], v2, qB);
    C1 = ffma2(C1, v2, qA);
    ull C2 = ffma2(c[11], v1, c[4]);
    C2 = ffma2(c[12], v2, C2);
    ull r = ffma2(c[10], v0, C2);
    r = ffma2(r, v0, C1);
    r = ffma2(r, v0, C0);
    return r;
}

__global__ __launch_bounds__(TPB, 2) void channel_poly_kernel(
    const float* __restrict__ img,     // (B, 3, H, W)
    const float* __restrict__ coeffs,  // (B, 3, 20)
    float* __restrict__ out)           // (B, 3, H, W)
{
    __shared__ ull sc2[3 * NCOEF];     // this batch's 60 splat pairs
    const int b = blockIdx.y;
    const int t = threadIdx.x;
    if (t < 3 * NCOEF) {
        ull u = (ull)__float_as_uint(coeffs[b * (3 * NCOEF) + t]);
        sc2[t] = u | (u << 32);        // splat {c, c}
    }
    __syncthreads();                   // the only barrier

    const ulonglong2* __restrict__ in =
        reinterpret_cast<const ulonglong2*>(img + (size_t)b * 3 * HW_PIX);
    ulonglong2* __restrict__ op =
        reinterpret_cast<ulonglong2*>(out + (size_t)b * 3 * HW_PIX);

    int i = blockIdx.x * TPB + t;      // < 4608 < HALF4 always

    // Prefetch first item (6 LDG.128).
    ulonglong2 a0 = in[i],         a1 = in[i + PLANE4],
               a2 = in[i + 2 * PLANE4];
    ulonglong2 b0 = in[i + HALF4], b1 = in[i + HALF4 + PLANE4],
               b2 = in[i + HALF4 + 2 * PLANE4];

#pragma unroll 1
    while (i < HALF4) {
        // Issue next item's 6 loads before computing this one
        // (keeps MLP=6 continuously outstanding per thread).
        const int inext = i + STRIDE;
        const int il = (inext < HALF4) ? inext : i;  // safe addr; unused on tail
        const ulonglong2 na0 = in[il],         na1 = in[il + PLANE4],
                         na2 = in[il + 2 * PLANE4];
        const ulonglong2 nb0 = in[il + HALF4], nb1 = in[il + HALF4 + PLANE4],
                         nb2 = in[il + HALF4 + 2 * PLANE4];

#pragma unroll 1
        for (int oc = 0; oc < 3; oc++) {
            const ull* __restrict__ c = sc2 + oc * NCOEF;
            ulonglong2 ra, rb;
            ra.x = horner2(a0.x, a1.x, a2.x, c);
            ra.y = horner2(a0.y, a1.y, a2.y, c);
            rb.x = horner2(b0.x, b1.x, b2.x, c);
            rb.y = horner2(b0.y, b1.y, b2.y, c);
            op[i + oc * PLANE4] = ra;
            op[i + HALF4 + oc * PLANE4] = rb;
        }

        // Rotate pipeline.
        i = inext;
        a0 = na0; a1 = na1; a2 = na2;
        b0 = nb0; b1 = nb1; b2 = nb2;
    }
}

extern "C" void kernel_launch(void* const* d_in, const int* in_sizes, int n_in,
                              void* d_out, int out_size) {
    const float* img = (const float*)d_in[0];     // (16,3,512,512)
    const float* coeffs = (const float*)d_in[1];  // (16,3,20)
    float* out = (float*)d_out;

    dim3 grid(CTAS_X, NBATCH, 1);                 // 18 x 16 = 288 CTAs
    channel_poly_kernel<<<grid, TPB>>>(img, coeffs, out);
}